// round 8
// baseline (speedup 1.0000x reference)
#include <cuda_runtime.h>
#include <cuda_bf16.h>
#include <mma.h>

using namespace nvcuda;

#define TB 16      // batch
#define TT 128     // time steps
#define TE 1024    // embed dim
#define TH 1024    // hidden dim
#define TV 32000   // vocab
#define BH (TB*TH)

// ---------------- scratch state (device globals: allocation-free) ----------
__device__ float g_x[(size_t)TT * TB * TE];       // [T][B][E] gathered embeddings
__device__ float g_h0[2][BH];
__device__ float g_c0[2][BH];
__device__ float g_h1[2][BH];
__device__ float g_c1[2][BH];
__device__ float g_feats[(size_t)TB * TT * TH];   // [B][T][H]
__device__ float g_zero[BH];                      // never written -> stays 0

// ---------------- embedding gather ----------------------------------------
__global__ void embed_gather_kernel(const int* __restrict__ ids,
                                    const float* __restrict__ embed) {
    int tb = blockIdx.x;            // t*TB + b
    int t  = tb >> 4;
    int b  = tb & 15;
    int id = ids[b * TT + t];
    const float4* src = (const float4*)(embed + (size_t)id * TE);
    float4*       dst = (float4*)(g_x + (size_t)tb * TE);
    dst[threadIdx.x] = src[threadIdx.x];   // 256 threads x float4 = 1024
}

// ---------------- state init ----------------------------------------------
__global__ void init_states_kernel(const float* __restrict__ eh,
                                   const float* __restrict__ ec) {
    int i = blockIdx.x * blockDim.x + threadIdx.x;   // BH total
    g_h0[0][i] = eh[i];
    g_h1[0][i] = eh[BH + i];
    g_c0[0][i] = ec[i];
    g_c1[0][i] = ec[BH + i];
}

// ---------------- LSTM step core ------------------------------------------
__device__ __forceinline__ float sigmoidf_(float x) {
    return 1.0f / (1.0f + __expf(-x));
}

// One source phase of K=1024: accumulate all 4 gates x 16 batches for unit j.
// src: [16][1024] activations; wmat row-major with row stride wstride; column
// offset coff selects which 1024-column slab of the weight matrix to use.
__device__ __forceinline__ void lstm_phase(
    const float* __restrict__ src, const float* __restrict__ wmat,
    int wstride, int coff, int j, int lane,
    float (&acc)[4][16], float (*s_in)[128])
{
    for (int c = 0; c < 8; ++c) {
        // cooperative load of 16x128 activation chunk (2048 floats / 256 thr)
        const float4* s4 = (const float4*)src;
        #pragma unroll
        for (int i = 0; i < 2; ++i) {
            int slot = threadIdx.x + (i << 8);   // 0..511 float4 slots
            int b  = slot >> 5;
            int kk = slot & 31;
            ((float4*)s_in[b])[kk] = s4[(b << 8) + (c << 5) + kk];
        }
        __syncthreads();

        int col = coff + (c << 7) + (lane << 2);
        float4 wv0 = *(const float4*)&wmat[(size_t)(0 * TH + j) * wstride + col];
        float4 wv1 = *(const float4*)&wmat[(size_t)(1 * TH + j) * wstride + col];
        float4 wv2 = *(const float4*)&wmat[(size_t)(2 * TH + j) * wstride + col];
        float4 wv3 = *(const float4*)&wmat[(size_t)(3 * TH + j) * wstride + col];

        #pragma unroll
        for (int b = 0; b < 16; ++b) {
            float4 xv = *(const float4*)&s_in[b][lane << 2];
            acc[0][b] += wv0.x * xv.x + wv0.y * xv.y + wv0.z * xv.z + wv0.w * xv.w;
            acc[1][b] += wv1.x * xv.x + wv1.y * xv.y + wv1.z * xv.z + wv1.w * xv.w;
            acc[2][b] += wv2.x * xv.x + wv2.y * xv.y + wv2.z * xv.z + wv2.w * xv.w;
            acc[3][b] += wv3.x * xv.x + wv3.y * xv.y + wv3.z * xv.z + wv3.w * xv.w;
        }
        __syncthreads();
    }
}

__device__ __forceinline__ void lstm_finish(
    float (&acc)[4][16], float (*s_red)[64], int warp, int lane, int j,
    const float* __restrict__ cprev,
    const float* __restrict__ bih, const float* __restrict__ bhh,
    float* __restrict__ hout, float* __restrict__ cout,
    float* __restrict__ feats, int t)
{
    // warp butterfly reduce each of the 64 partial sums
    #pragma unroll
    for (int g = 0; g < 4; ++g)
        #pragma unroll
        for (int b = 0; b < 16; ++b)
            #pragma unroll
            for (int off = 16; off; off >>= 1)
                acc[g][b] += __shfl_xor_sync(0xffffffffu, acc[g][b], off);

    if (lane == 0) {
        #pragma unroll
        for (int g = 0; g < 4; ++g)
            #pragma unroll
            for (int b = 0; b < 16; ++b)
                s_red[warp][g * 16 + b] = acc[g][b];
    }
    __syncwarp();

    if (lane < 16) {
        int b = lane;
        float gi = s_red[warp][0 * 16 + b] + bih[j]           + bhh[j];
        float gf = s_red[warp][1 * 16 + b] + bih[TH + j]      + bhh[TH + j];
        float gg = s_red[warp][2 * 16 + b] + bih[2 * TH + j]  + bhh[2 * TH + j];
        float go = s_red[warp][3 * 16 + b] + bih[3 * TH + j]  + bhh[3 * TH + j];
        float cold = cprev[b * TH + j];
        float cn = sigmoidf_(gf) * cold + sigmoidf_(gi) * tanhf(gg);
        float hn = sigmoidf_(go) * tanhf(cn);
        cout[b * TH + j] = cn;
        hout[b * TH + j] = hn;
        if (feats) feats[((size_t)b * TT + t) * TH + j] = hn;
    }
}

__global__ __launch_bounds__(256) void lstm_layer0_kernel(
    const float* __restrict__ Wih, const float* __restrict__ Whh,
    const float* __restrict__ bih, const float* __restrict__ bhh, int t)
{
    __shared__ float s_in[16][128];
    __shared__ float s_red[8][64];
    int warp = threadIdx.x >> 5, lane = threadIdx.x & 31;
    int j = (blockIdx.x << 3) + warp;

    float acc[4][16];
    #pragma unroll
    for (int g = 0; g < 4; ++g)
        #pragma unroll
        for (int b = 0; b < 16; ++b) acc[g][b] = 0.f;

    int r = t & 1, w = 1 - r;
    const float* xsrc = g_x + (size_t)t * TB * TE;
    const float* feed = (t == 0) ? g_zero : g_h1[r];

    lstm_phase(xsrc,    Wih, 2048, 0,    j, lane, acc, s_in);
    lstm_phase(feed,    Wih, 2048, 1024, j, lane, acc, s_in);
    lstm_phase(g_h0[r], Whh, 1024, 0,    j, lane, acc, s_in);

    lstm_finish(acc, s_red, warp, lane, j, g_c0[r], bih, bhh,
                g_h0[w], g_c0[w], nullptr, t);
}

__global__ __launch_bounds__(256) void lstm_layer1_kernel(
    const float* __restrict__ Wih, const float* __restrict__ Whh,
    const float* __restrict__ bih, const float* __restrict__ bhh, int t)
{
    __shared__ float s_in[16][128];
    __shared__ float s_red[8][64];
    int warp = threadIdx.x >> 5, lane = threadIdx.x & 31;
    int j = (blockIdx.x << 3) + warp;

    float acc[4][16];
    #pragma unroll
    for (int g = 0; g < 4; ++g)
        #pragma unroll
        for (int b = 0; b < 16; ++b) acc[g][b] = 0.f;

    int r = t & 1, w = 1 - r;

    lstm_phase(g_h0[w], Wih, 1024, 0, j, lane, acc, s_in);  // new h0 (this step)
    lstm_phase(g_h1[r], Whh, 1024, 0, j, lane, acc, s_in);

    lstm_finish(acc, s_red, warp, lane, j, g_c1[r], bih, bhh,
                g_h1[w], g_c1[w], g_feats, t);
}

// ---------------- output projection: tf32 WMMA GEMM ------------------------
// logits[m, n] = sum_k feats[m, k] * Wout[n, k] + bout[n]
// CTA tile 64x64, 4 warps (2x2), warp tile 32x32 via 2x2 m16n16k8 fragments.
__global__ __launch_bounds__(128) void proj_kernel(
    const float* __restrict__ Wout, const float* __restrict__ bout,
    float* __restrict__ out)
{
    __shared__ float smem[2 * 64 * 40];
    float (*sA)[40] = (float(*)[40])smem;
    float (*sB)[40] = (float(*)[40])(smem + 64 * 40);

    int mblk = blockIdx.x << 6;
    int nblk = blockIdx.y << 6;
    int warp = threadIdx.x >> 5;
    int wm = (warp >> 1) * 32;
    int wn = (warp & 1) * 32;

    wmma::fragment<wmma::accumulator, 16, 16, 8, float> cf[2][2];
    #pragma unroll
    for (int mi = 0; mi < 2; ++mi)
        #pragma unroll
        for (int ni = 0; ni < 2; ++ni)
            wmma::fill_fragment(cf[mi][ni], 0.0f);

    const float* A = g_feats;
    for (int k0 = 0; k0 < 1024; k0 += 32) {
        #pragma unroll
        for (int i = 0; i < 4; ++i) {
            int slot = threadIdx.x + (i << 7);  // 0..511 float4 slots
            int row  = slot >> 3;
            int c4   = (slot & 7) << 2;
            *(float4*)&sA[row][c4] =
                *(const float4*)&A[(size_t)(mblk + row) * 1024 + k0 + c4];
            *(float4*)&sB[row][c4] =
                *(const float4*)&Wout[(size_t)(nblk + row) * 1024 + k0 + c4];
        }
        __syncthreads();

        #pragma unroll
        for (int kk = 0; kk < 32; kk += 8) {
            wmma::fragment<wmma::matrix_a, 16, 16, 8,
                           wmma::precision::tf32, wmma::row_major> af[2];
            wmma::fragment<wmma::matrix_b, 16, 16, 8,
                           wmma::precision::tf32, wmma::col_major> bf[2];
            #pragma unroll
            for (int i = 0; i < 2; ++i) {
                wmma::load_matrix_sync(af[i], &sA[wm + i * 16][kk], 40);
                #pragma unroll
                for (int e = 0; e < af[i].num_elements; ++e)
                    af[i].x[e] = wmma::__float_to_tf32(af[i].x[e]);
                wmma::load_matrix_sync(bf[i], &sB[wn + i * 16][kk], 40);
                #pragma unroll
                for (int e = 0; e < bf[i].num_elements; ++e)
                    bf[i].x[e] = wmma::__float_to_tf32(bf[i].x[e]);
            }
            #pragma unroll
            for (int mi = 0; mi < 2; ++mi)
                #pragma unroll
                for (int ni = 0; ni < 2; ++ni)
                    wmma::mma_sync(cf[mi][ni], af[mi], bf[ni], cf[mi][ni]);
        }
        __syncthreads();
    }

    // epilogue: stage C in smem, add bias, vectorized store
    float (*sC)[68] = (float(*)[68])smem;   // 64*68 = 4352 floats <= 5120
    #pragma unroll
    for (int mi = 0; mi < 2; ++mi)
        #pragma unroll
        for (int ni = 0; ni < 2; ++ni)
            wmma::store_matrix_sync(&sC[wm + mi * 16][wn + ni * 16],
                                    cf[mi][ni], 68, wmma::mem_row_major);
    __syncthreads();

    #pragma unroll
    for (int i = 0; i < 8; ++i) {
        int slot = threadIdx.x + (i << 7);  // 0..1023 float4 slots
        int row  = slot >> 4;
        int c4   = (slot & 15) << 2;
        float4 v  = *(float4*)&sC[row][c4];
        float4 bv = *(const float4*)&bout[nblk + c4];
        v.x += bv.x; v.y += bv.y; v.z += bv.z; v.w += bv.w;
        *(float4*)&out[(size_t)(mblk + row) * TV + nblk + c4] = v;
    }
}

// ---------------- launch ----------------------------------------------------
extern "C" void kernel_launch(void* const* d_in, const int* in_sizes, int n_in,
                              void* d_out, int out_size) {
    const int*   ids  = (const int*)d_in[0];
    const float* ench = (const float*)d_in[1];
    const float* encc = (const float*)d_in[2];
    const float* emb  = (const float*)d_in[3];
    const float* Wih0 = (const float*)d_in[4];
    const float* Whh0 = (const float*)d_in[5];
    const float* bih0 = (const float*)d_in[6];
    const float* bhh0 = (const float*)d_in[7];
    const float* Wih1 = (const float*)d_in[8];
    const float* Whh1 = (const float*)d_in[9];
    const float* bih1 = (const float*)d_in[10];
    const float* bhh1 = (const float*)d_in[11];
    const float* Wout = (const float*)d_in[12];
    const float* bout = (const float*)d_in[13];
    float* out = (float*)d_out;

    embed_gather_kernel<<<TT * TB, 256>>>(ids, emb);
    init_states_kernel<<<64, 256>>>(ench, encc);

    for (int t = 0; t < TT; ++t) {
        lstm_layer0_kernel<<<128, 256>>>(Wih0, Whh0, bih0, bhh0, t);
        lstm_layer1_kernel<<<128, 256>>>(Wih1, Whh1, bih1, bhh1, t);
    }

    proj_kernel<<<dim3(32, 500), 128>>>(Wout, bout, out);
}

// round 9
// speedup vs baseline: 1.0051x; 1.0051x over previous
#include <cuda_runtime.h>
#include <cuda_bf16.h>
#include <mma.h>

using namespace nvcuda;

#define TB 16      // batch
#define TT 128     // time steps
#define TE 1024    // embed dim
#define TH 1024    // hidden dim
#define TV 32000   // vocab
#define BH (TB*TH)

// ---------------- scratch state (device globals: allocation-free) ----------
__device__ float g_x[(size_t)TT * TB * TE];       // [T][B][E] gathered embeddings
__device__ float g_h0[2][BH];
__device__ float g_c0[2][BH];
__device__ float g_h1[2][BH];
__device__ float g_c1[2][BH];
__device__ float g_feats[(size_t)TB * TT * TH];   // [B][T][H]
__device__ float g_zero[BH];                      // never written -> stays 0

// ---------------- embedding gather ----------------------------------------
__global__ void embed_gather_kernel(const int* __restrict__ ids,
                                    const float* __restrict__ embed) {
    int tb = blockIdx.x;            // t*TB + b
    int t  = tb >> 4;
    int b  = tb & 15;
    int id = ids[b * TT + t];
    const float4* src = (const float4*)(embed + (size_t)id * TE);
    float4*       dst = (float4*)(g_x + (size_t)tb * TE);
    dst[threadIdx.x] = src[threadIdx.x];   // 256 threads x float4 = 1024
}

// ---------------- state init ----------------------------------------------
__global__ void init_states_kernel(const float* __restrict__ eh,
                                   const float* __restrict__ ec) {
    int i = blockIdx.x * blockDim.x + threadIdx.x;   // BH total
    g_h0[0][i] = eh[i];
    g_h1[0][i] = eh[BH + i];
    g_c0[0][i] = ec[i];
    g_c1[0][i] = ec[BH + i];
}

// ---------------- LSTM step core ------------------------------------------
__device__ __forceinline__ float sigmoidf_(float x) {
    return 1.0f / (1.0f + __expf(-x));
}

// One source phase of K=1024: accumulate all 4 gates x 16 batches for unit j.
// src: [16][1024] activations; wmat row-major with row stride wstride; column
// offset coff selects which 1024-column slab of the weight matrix to use.
__device__ __forceinline__ void lstm_phase(
    const float* __restrict__ src, const float* __restrict__ wmat,
    int wstride, int coff, int j, int lane,
    float (&acc)[4][16], float (*s_in)[128])
{
    for (int c = 0; c < 8; ++c) {
        // cooperative load of 16x128 activation chunk (2048 floats / 256 thr)
        const float4* s4 = (const float4*)src;
        #pragma unroll
        for (int i = 0; i < 2; ++i) {
            int slot = threadIdx.x + (i << 8);   // 0..511 float4 slots
            int b  = slot >> 5;
            int kk = slot & 31;
            ((float4*)s_in[b])[kk] = s4[(b << 8) + (c << 5) + kk];
        }
        __syncthreads();

        int col = coff + (c << 7) + (lane << 2);
        float4 wv0 = *(const float4*)&wmat[(size_t)(0 * TH + j) * wstride + col];
        float4 wv1 = *(const float4*)&wmat[(size_t)(1 * TH + j) * wstride + col];
        float4 wv2 = *(const float4*)&wmat[(size_t)(2 * TH + j) * wstride + col];
        float4 wv3 = *(const float4*)&wmat[(size_t)(3 * TH + j) * wstride + col];

        #pragma unroll
        for (int b = 0; b < 16; ++b) {
            float4 xv = *(const float4*)&s_in[b][lane << 2];
            acc[0][b] += wv0.x * xv.x + wv0.y * xv.y + wv0.z * xv.z + wv0.w * xv.w;
            acc[1][b] += wv1.x * xv.x + wv1.y * xv.y + wv1.z * xv.z + wv1.w * xv.w;
            acc[2][b] += wv2.x * xv.x + wv2.y * xv.y + wv2.z * xv.z + wv2.w * xv.w;
            acc[3][b] += wv3.x * xv.x + wv3.y * xv.y + wv3.z * xv.z + wv3.w * xv.w;
        }
        __syncthreads();
    }
}

__device__ __forceinline__ void lstm_finish(
    float (&acc)[4][16], float (*s_red)[64], int warp, int lane, int j,
    const float* __restrict__ cprev,
    const float* __restrict__ bih, const float* __restrict__ bhh,
    float* __restrict__ hout, float* __restrict__ cout,
    float* __restrict__ feats, int t)
{
    // warp butterfly reduce each of the 64 partial sums
    #pragma unroll
    for (int g = 0; g < 4; ++g)
        #pragma unroll
        for (int b = 0; b < 16; ++b)
            #pragma unroll
            for (int off = 16; off; off >>= 1)
                acc[g][b] += __shfl_xor_sync(0xffffffffu, acc[g][b], off);

    if (lane == 0) {
        #pragma unroll
        for (int g = 0; g < 4; ++g)
            #pragma unroll
            for (int b = 0; b < 16; ++b)
                s_red[warp][g * 16 + b] = acc[g][b];
    }
    __syncwarp();

    if (lane < 16) {
        int b = lane;
        float gi = s_red[warp][0 * 16 + b] + bih[j]           + bhh[j];
        float gf = s_red[warp][1 * 16 + b] + bih[TH + j]      + bhh[TH + j];
        float gg = s_red[warp][2 * 16 + b] + bih[2 * TH + j]  + bhh[2 * TH + j];
        float go = s_red[warp][3 * 16 + b] + bih[3 * TH + j]  + bhh[3 * TH + j];
        float cold = cprev[b * TH + j];
        float cn = sigmoidf_(gf) * cold + sigmoidf_(gi) * tanhf(gg);
        float hn = sigmoidf_(go) * tanhf(cn);
        cout[b * TH + j] = cn;
        hout[b * TH + j] = hn;
        if (feats) feats[((size_t)b * TT + t) * TH + j] = hn;
    }
}

__global__ __launch_bounds__(256) void lstm_layer0_kernel(
    const float* __restrict__ Wih, const float* __restrict__ Whh,
    const float* __restrict__ bih, const float* __restrict__ bhh, int t)
{
    __shared__ float s_in[16][128];
    __shared__ float s_red[8][64];
    int warp = threadIdx.x >> 5, lane = threadIdx.x & 31;
    int j = (blockIdx.x << 3) + warp;

    float acc[4][16];
    #pragma unroll
    for (int g = 0; g < 4; ++g)
        #pragma unroll
        for (int b = 0; b < 16; ++b) acc[g][b] = 0.f;

    int r = t & 1, w = 1 - r;
    const float* xsrc = g_x + (size_t)t * TB * TE;
    const float* feed = (t == 0) ? g_zero : g_h1[r];

    lstm_phase(xsrc,    Wih, 2048, 0,    j, lane, acc, s_in);
    lstm_phase(feed,    Wih, 2048, 1024, j, lane, acc, s_in);
    lstm_phase(g_h0[r], Whh, 1024, 0,    j, lane, acc, s_in);

    lstm_finish(acc, s_red, warp, lane, j, g_c0[r], bih, bhh,
                g_h0[w], g_c0[w], nullptr, t);
}

__global__ __launch_bounds__(256) void lstm_layer1_kernel(
    const float* __restrict__ Wih, const float* __restrict__ Whh,
    const float* __restrict__ bih, const float* __restrict__ bhh, int t)
{
    __shared__ float s_in[16][128];
    __shared__ float s_red[8][64];
    int warp = threadIdx.x >> 5, lane = threadIdx.x & 31;
    int j = (blockIdx.x << 3) + warp;

    float acc[4][16];
    #pragma unroll
    for (int g = 0; g < 4; ++g)
        #pragma unroll
        for (int b = 0; b < 16; ++b) acc[g][b] = 0.f;

    int r = t & 1, w = 1 - r;

    lstm_phase(g_h0[w], Wih, 1024, 0, j, lane, acc, s_in);  // new h0 (this step)
    lstm_phase(g_h1[r], Whh, 1024, 0, j, lane, acc, s_in);

    lstm_finish(acc, s_red, warp, lane, j, g_c1[r], bih, bhh,
                g_h1[w], g_c1[w], g_feats, t);
}

// ---------------- output projection: tf32 WMMA GEMM ------------------------
// logits[m, n] = sum_k feats[m, k] * Wout[n, k] + bout[n]
// CTA tile 64x64, 4 warps (2x2), warp tile 32x32 via 2x2 m16n16k8 fragments.
__global__ __launch_bounds__(128) void proj_kernel(
    const float* __restrict__ Wout, const float* __restrict__ bout,
    float* __restrict__ out)
{
    __shared__ float smem[2 * 64 * 40];
    float (*sA)[40] = (float(*)[40])smem;
    float (*sB)[40] = (float(*)[40])(smem + 64 * 40);

    int mblk = blockIdx.x << 6;
    int nblk = blockIdx.y << 6;
    int warp = threadIdx.x >> 5;
    int wm = (warp >> 1) * 32;
    int wn = (warp & 1) * 32;

    wmma::fragment<wmma::accumulator, 16, 16, 8, float> cf[2][2];
    #pragma unroll
    for (int mi = 0; mi < 2; ++mi)
        #pragma unroll
        for (int ni = 0; ni < 2; ++ni)
            wmma::fill_fragment(cf[mi][ni], 0.0f);

    const float* A = g_feats;
    for (int k0 = 0; k0 < 1024; k0 += 32) {
        #pragma unroll
        for (int i = 0; i < 4; ++i) {
            int slot = threadIdx.x + (i << 7);  // 0..511 float4 slots
            int row  = slot >> 3;
            int c4   = (slot & 7) << 2;
            *(float4*)&sA[row][c4] =
                *(const float4*)&A[(size_t)(mblk + row) * 1024 + k0 + c4];
            *(float4*)&sB[row][c4] =
                *(const float4*)&Wout[(size_t)(nblk + row) * 1024 + k0 + c4];
        }
        __syncthreads();

        #pragma unroll
        for (int kk = 0; kk < 32; kk += 8) {
            wmma::fragment<wmma::matrix_a, 16, 16, 8,
                           wmma::precision::tf32, wmma::row_major> af[2];
            wmma::fragment<wmma::matrix_b, 16, 16, 8,
                           wmma::precision::tf32, wmma::col_major> bf[2];
            #pragma unroll
            for (int i = 0; i < 2; ++i) {
                wmma::load_matrix_sync(af[i], &sA[wm + i * 16][kk], 40);
                #pragma unroll
                for (int e = 0; e < af[i].num_elements; ++e)
                    af[i].x[e] = wmma::__float_to_tf32(af[i].x[e]);
                wmma::load_matrix_sync(bf[i], &sB[wn + i * 16][kk], 40);
                #pragma unroll
                for (int e = 0; e < bf[i].num_elements; ++e)
                    bf[i].x[e] = wmma::__float_to_tf32(bf[i].x[e]);
            }
            #pragma unroll
            for (int mi = 0; mi < 2; ++mi)
                #pragma unroll
                for (int ni = 0; ni < 2; ++ni)
                    wmma::mma_sync(cf[mi][ni], af[mi], bf[ni], cf[mi][ni]);
        }
        __syncthreads();
    }

    // epilogue: stage C in smem, add bias, vectorized store
    float (*sC)[68] = (float(*)[68])smem;   // 64*68 = 4352 floats <= 5120
    #pragma unroll
    for (int mi = 0; mi < 2; ++mi)
        #pragma unroll
        for (int ni = 0; ni < 2; ++ni)
            wmma::store_matrix_sync(&sC[wm + mi * 16][wn + ni * 16],
                                    cf[mi][ni], 68, wmma::mem_row_major);
    __syncthreads();

    #pragma unroll
    for (int i = 0; i < 8; ++i) {
        int slot = threadIdx.x + (i << 7);  // 0..1023 float4 slots
        int row  = slot >> 4;
        int c4   = (slot & 15) << 2;
        float4 v  = *(float4*)&sC[row][c4];
        float4 bv = *(const float4*)&bout[nblk + c4];
        v.x += bv.x; v.y += bv.y; v.z += bv.z; v.w += bv.w;
        *(float4*)&out[(size_t)(mblk + row) * TV + nblk + c4] = v;
    }
}

// ---------------- launch ----------------------------------------------------
extern "C" void kernel_launch(void* const* d_in, const int* in_sizes, int n_in,
                              void* d_out, int out_size) {
    const int*   ids  = (const int*)d_in[0];
    const float* ench = (const float*)d_in[1];
    const float* encc = (const float*)d_in[2];
    const float* emb  = (const float*)d_in[3];
    const float* Wih0 = (const float*)d_in[4];
    const float* Whh0 = (const float*)d_in[5];
    const float* bih0 = (const float*)d_in[6];
    const float* bhh0 = (const float*)d_in[7];
    const float* Wih1 = (const float*)d_in[8];
    const float* Whh1 = (const float*)d_in[9];
    const float* bih1 = (const float*)d_in[10];
    const float* bhh1 = (const float*)d_in[11];
    const float* Wout = (const float*)d_in[12];
    const float* bout = (const float*)d_in[13];
    float* out = (float*)d_out;

    embed_gather_kernel<<<TT * TB, 256>>>(ids, emb);
    init_states_kernel<<<64, 256>>>(ench, encc);

    for (int t = 0; t < TT; ++t) {
        lstm_layer0_kernel<<<128, 256>>>(Wih0, Whh0, bih0, bhh0, t);
        lstm_layer1_kernel<<<128, 256>>>(Wih1, Whh1, bih1, bhh1, t);
    }

    proj_kernel<<<dim3(32, 500), 128>>>(Wout, bout, out);
}